// round 7
// baseline (speedup 1.0000x reference)
#include <cuda_runtime.h>
#include <cuda_bf16.h>
#include <stdint.h>
#include <math.h>

#define B_N 4096
#define D_N 2048
#define C_N 64

#define BTM 256           // CTA tile M
#define BTN 128           // CTA tile N
#define BKS 64            // K per stage (bf16) = 128B per row
#define STAGES 3
#define A_TILE_B (BTM*128)              // 32768
#define B_TILE_B (BTN*128)              // 16384
#define STAGE_B  (A_TILE_B + B_TILE_B)  // 49152
#define SMEM_TOTAL (1024 + STAGES*STAGE_B)   // 148480

// ---------------- scratch (static device globals) ----------------
__device__ __align__(128) __nv_bfloat16 g_xbf[B_N * D_N];            // 16 MB
__device__ __align__(128) __nv_bfloat16 g_xT[D_N * B_N];             // 16 MB
__device__ __align__(128) __nv_bfloat16 g_expSbf[(size_t)B_N * B_N]; // 32 MB
__device__ __align__(128) float g_R[B_N * D_N];                      // 32 MB
__device__ float g_rowsum[B_N];
__device__ float g_keep[B_N];
__device__ float g_contrib[B_N];

// ---------------- PTX helpers (sm_80+ generic ISA only) ----------------
__device__ __forceinline__ uint32_t smem_u32(const void* p) {
    uint32_t a;
    asm("{ .reg .u64 t; cvta.to.shared.u64 t, %1; cvt.u32.u64 %0, t; }" : "=r"(a) : "l"(p));
    return a;
}
__device__ __forceinline__ void cp16(uint32_t s, const void* g) {
    asm volatile("cp.async.cg.shared.global [%0], [%1], 16;" :: "r"(s), "l"(g));
}
__device__ __forceinline__ void cp_commit() { asm volatile("cp.async.commit_group;"); }
__device__ __forceinline__ void cp_wait1()  { asm volatile("cp.async.wait_group 1;"); }

__device__ __forceinline__ void ldsm4(uint32_t* r, uint32_t addr) {
    asm volatile("ldmatrix.sync.aligned.m8n8.x4.shared.b16 {%0,%1,%2,%3}, [%4];"
        : "=r"(r[0]), "=r"(r[1]), "=r"(r[2]), "=r"(r[3]) : "r"(addr));
}
__device__ __forceinline__ void mma_bf16(float* c, const uint32_t* a, uint32_t b0, uint32_t b1) {
    asm volatile(
        "mma.sync.aligned.m16n8k16.row.col.f32.bf16.bf16.f32 "
        "{%0,%1,%2,%3}, {%4,%5,%6,%7}, {%8,%9}, {%0,%1,%2,%3};"
        : "+f"(c[0]), "+f"(c[1]), "+f"(c[2]), "+f"(c[3])
        : "r"(a[0]), "r"(a[1]), "r"(a[2]), "r"(a[3]), "r"(b0), "r"(b1));
}

// ---------------- small kernels ----------------
__global__ void k_prep(const int* __restrict__ y, const float* __restrict__ c,
                       const int* __restrict__ fs) {
    int i = blockIdx.x * blockDim.x + threadIdx.x;
    if (i < B_N) {
        int cls = y[i];
        g_contrib[i] = c[cls];
        g_keep[i] = fs[cls] ? 0.0f : 1.0f;
        g_rowsum[i] = 0.0f;
    }
}

__global__ __launch_bounds__(256) void k_lnorm(const float* __restrict__ x) {
    int row = blockIdx.x;
    const float* xr = x + (size_t)row * D_N;
    float s = 0.f, s2 = 0.f;
    for (int d = threadIdx.x; d < D_N; d += 256) {
        float v = xr[d];
        s += v; s2 += v * v;
    }
    __shared__ float sh[34];
    #pragma unroll
    for (int o = 16; o > 0; o >>= 1) {
        s  += __shfl_down_sync(0xffffffffu, s, o);
        s2 += __shfl_down_sync(0xffffffffu, s2, o);
    }
    int w = threadIdx.x >> 5, l = threadIdx.x & 31;
    if (l == 0) { sh[w] = s; sh[8 + w] = s2; }
    __syncthreads();
    if (threadIdx.x == 0) {
        float S = 0.f, S2 = 0.f;
        #pragma unroll
        for (int i = 0; i < 8; i++) { S += sh[i]; S2 += sh[8 + i]; }
        float mu = S / (float)D_N;
        float var = S2 / (float)D_N - mu * mu;
        sh[32] = mu;
        sh[33] = rsqrtf(var + 1e-5f) * rsqrtf((float)D_N);
    }
    __syncthreads();
    float mu = sh[32], sc = sh[33];
    __nv_bfloat16* xo = g_xbf + (size_t)row * D_N;
    for (int d = threadIdx.x; d < D_N; d += 256)
        xo[d] = __float2bfloat16((xr[d] - mu) * sc);
}

// x [B_N, D_N] fp32 -> g_xT [D_N, B_N] bf16
__global__ __launch_bounds__(256) void k_transpose(const float* __restrict__ x) {
    __shared__ float tile[32][33];
    int bk = blockIdx.x * 32;   // over B_N
    int bn = blockIdx.y * 32;   // over D_N
    int tx = threadIdx.x & 31, ty = threadIdx.x >> 5;
    #pragma unroll
    for (int i = 0; i < 32; i += 8)
        tile[ty + i][tx] = x[(size_t)(bk + ty + i) * D_N + bn + tx];
    __syncthreads();
    #pragma unroll
    for (int i = 0; i < 32; i += 8)
        g_xT[(size_t)(bn + ty + i) * B_N + bk + tx] = __float2bfloat16(tile[tx][ty + i]);
}

// ---------------- mma.sync GEMM: C[MxN] = A[M,K] . B[N,K]^T ----------------
// CTA 256x128, 8 warps: 4(m) x 2(n), warp tile 64x64.
// Per k16 step: 4 A ldsm4 + 4 B ldsm4 (4KB smem) feed 32 MMA (128 B/MMA).
// SW128 swizzle rows of 128B; k-step kk address = base ^ (kk<<5).
template<int KTOT, bool EPI1>
__global__ __launch_bounds__(256, 1) void k_mma(const float* __restrict__ x) {
    extern __shared__ char smem[];
    const uint32_t smem_raw = smem_u32(smem);
    const uint32_t tiles0 = (smem_raw + 1023u) & ~1023u;
    const int t = threadIdx.x;
    const int wid = t >> 5, lane = t & 31;
    const int bm = blockIdx.y, bn = blockIdx.x;
    const int KC = KTOT / BKS;

    const __nv_bfloat16* A  = EPI1 ? g_xbf : g_expSbf;
    const __nv_bfloat16* Bm = EPI1 ? g_xbf : g_xT;

    const int warp_m0 = (wid >> 1) * 64;   // 0,64,128,192
    const int warp_n0 = (wid & 1) * 64;    // 0,64
    const int rowA0 = bm * BTM;
    const int rowB0 = bn * BTN;

    uint32_t sA[STAGES], sB[STAGES];
    #pragma unroll
    for (int s = 0; s < STAGES; s++) {
        sA[s] = tiles0 + (uint32_t)s * STAGE_B;
        sB[s] = sA[s] + A_TILE_B;
    }

    const int lr0 = t >> 3;      // 0..31
    const int cc = t & 7;        // 16B chunk in 128B row
    const uint32_t soff0 = (uint32_t)(lr0 * 128 + ((cc ^ (lr0 & 7)) * 16));

    const __nv_bfloat16* gA = A  + (size_t)(rowA0 + lr0) * KTOT + cc * 8;
    const __nv_bfloat16* gB = Bm + (size_t)(rowB0 + lr0) * KTOT + cc * 8;

    #define LOAD_STAGE(sidx, k0elem) do {                                              \
        _Pragma("unroll")                                                              \
        for (int _i = 0; _i < 8; _i++)                                                 \
            cp16(sA[sidx] + soff0 + (uint32_t)(_i * 32 * 128),                         \
                 gA + (size_t)_i * 32 * KTOT + (k0elem));                              \
        _Pragma("unroll")                                                              \
        for (int _i = 0; _i < 4; _i++)                                                 \
            cp16(sB[sidx] + soff0 + (uint32_t)(_i * 32 * 128),                         \
                 gB + (size_t)_i * 32 * KTOT + (k0elem));                              \
    } while (0)

    #pragma unroll
    for (int p = 0; p < STAGES - 1; p++) {
        LOAD_STAGE(p, p * BKS);
        cp_commit();
    }

    float acc[4][8][4];
    #pragma unroll
    for (int i = 0; i < 4; i++)
        #pragma unroll
        for (int j = 0; j < 8; j++)
            #pragma unroll
            for (int r = 0; r < 4; r++) acc[i][j][r] = 0.f;

    const int lrow = lane & 15;
    const int lhal = lane >> 4;
    uint32_t aoff[4], boff[4];
    #pragma unroll
    for (int im = 0; im < 4; im++) {
        int r = warp_m0 + im * 16 + lrow;
        aoff[im] = (uint32_t)(r * 128 + ((lhal ^ (r & 7)) << 4));
    }
    #pragma unroll
    for (int ib = 0; ib < 4; ib++) {
        int r = warp_n0 + ib * 16 + lrow;
        boff[ib] = (uint32_t)(r * 128 + ((lhal ^ (r & 7)) << 4));
    }

    for (int c = 0; c < KC; c++) {
        cp_wait1();
        __syncthreads();
        if (c + STAGES - 1 < KC) LOAD_STAGE((c + STAGES - 1) % STAGES, (c + STAGES - 1) * BKS);
        cp_commit();

        const uint32_t bufA = sA[c % STAGES];
        const uint32_t bufB = sB[c % STAGES];
        #pragma unroll
        for (int kk = 0; kk < 4; kk++) {
            const uint32_t kx = (uint32_t)(kk << 5);
            uint32_t a[4][4], b[4][4];
            #pragma unroll
            for (int im = 0; im < 4; im++)
                ldsm4(a[im], (bufA + aoff[im]) ^ kx);
            #pragma unroll
            for (int ib = 0; ib < 4; ib++)
                ldsm4(b[ib], (bufB + boff[ib]) ^ kx);
            #pragma unroll
            for (int im = 0; im < 4; im++) {
                #pragma unroll
                for (int ib = 0; ib < 4; ib++) {
                    mma_bf16(acc[im][ib * 2 + 0], a[im], b[ib][0], b[ib][2]);
                    mma_bf16(acc[im][ib * 2 + 1], a[im], b[ib][1], b[ib][3]);
                }
            }
        }
    }

    // ---- epilogue ----
    const int lq = lane >> 2;
    const int lp = lane & 3;
    int colg[8];
    #pragma unroll
    for (int j = 0; j < 8; j++)
        colg[j] = rowB0 + warp_n0 + j * 8 + 2 * lp;

    if (EPI1) {
        float kp0[8], kp1[8];
        #pragma unroll
        for (int j = 0; j < 8; j++) { kp0[j] = g_keep[colg[j]]; kp1[j] = g_keep[colg[j] + 1]; }
        #pragma unroll
        for (int im = 0; im < 4; im++) {
            #pragma unroll
            for (int h = 0; h < 2; h++) {
                int row = rowA0 + warp_m0 + im * 16 + h * 8 + lq;
                float rs = 0.f;
                #pragma unroll
                for (int j = 0; j < 8; j++) {
                    float w0 = (colg[j] == row) ? 0.f : kp0[j];
                    float w1 = (colg[j] + 1 == row) ? 0.f : kp1[j];
                    float v0 = w0 * __expf(acc[im][j][2 * h + 0]);
                    float v1 = w1 * __expf(acc[im][j][2 * h + 1]);
                    __nv_bfloat16 b0 = __float2bfloat16(v0);
                    __nv_bfloat16 b1 = __float2bfloat16(v1);
                    rs += __bfloat162float(b0) + __bfloat162float(b1);
                    __nv_bfloat162 p2(b0, b1);
                    *reinterpret_cast<uint32_t*>(g_expSbf + (size_t)row * B_N + colg[j]) =
                        *reinterpret_cast<uint32_t*>(&p2);
                }
                rs += __shfl_xor_sync(0xffffffffu, rs, 1);
                rs += __shfl_xor_sync(0xffffffffu, rs, 2);
                if (lp == 0) atomicAdd(&g_rowsum[row], rs);
            }
        }
    } else {
        #pragma unroll
        for (int im = 0; im < 4; im++) {
            #pragma unroll
            for (int h = 0; h < 2; h++) {
                int row = rowA0 + warp_m0 + im * 16 + h * 8 + lq;
                float ct = g_contrib[row];
                float s1 = ct / g_rowsum[row];     // fused reciprocal
                float s2 = 1.0f - ct;
                #pragma unroll
                for (int j = 0; j < 8; j++) {
                    const float2 xv = *(const float2*)(x + (size_t)row * D_N + colg[j]);
                    float2 o;
                    o.x = acc[im][j][2 * h + 0] * s1 + xv.x * s2;
                    o.y = acc[im][j][2 * h + 1] * s1 + xv.y * s2;
                    *(float2*)(g_R + (size_t)row * D_N + colg[j]) = o;
                }
            }
        }
    }
    #undef LOAD_STAGE
}

// ---------------- mix kernels ----------------
__global__ __launch_bounds__(256) void k_mixx(const float* __restrict__ alpha,
                                              const int* __restrict__ beta,
                                              float* __restrict__ out) {
    int idx = blockIdx.x * blockDim.x + threadIdx.x;
    const int nd4 = D_N / 4;
    if (idx < B_N * nd4) {
        int i = idx / nd4;
        int d4 = idx - i * nd4;
        float a = alpha[i];
        float na = 1.0f - a;
        int bi = beta[i];
        const float4* R4 = (const float4*)g_R;
        float4 r1 = R4[(size_t)i * nd4 + d4];
        float4 r2 = R4[(size_t)bi * nd4 + d4];
        float4 o;
        o.x = a * r1.x + na * r2.x;
        o.y = a * r1.y + na * r2.y;
        o.z = a * r1.z + na * r2.z;
        o.w = a * r1.w + na * r2.w;
        ((float4*)out)[idx] = o;
    }
}

__global__ void k_mixy(const float* __restrict__ alpha,
                       const int* __restrict__ beta,
                       const int* __restrict__ y,
                       float* __restrict__ out) {
    int idx = blockIdx.x * blockDim.x + threadIdx.x;
    if (idx < B_N * C_N) {
        int i = idx / C_N;
        int k = idx - i * C_N;
        float a = alpha[i];
        int bi = beta[i];
        float v = a * (k == y[i] ? 1.0f : 0.0f) + (1.0f - a) * (k == y[bi] ? 1.0f : 0.0f);
        out[(size_t)B_N * D_N + idx] = v;
    }
}

extern "C" void kernel_launch(void* const* d_in, const int* in_sizes, int n_in,
                              void* d_out, int out_size) {
    const float* x     = (const float*)d_in[0];
    const int*   y     = (const int*)  d_in[1];
    const float* alpha = (const float*)d_in[2];
    const int*   beta  = (const int*)  d_in[3];
    const float* c     = (const float*)d_in[4];
    const int*   fs    = (const int*)  d_in[5];
    float* out = (float*)d_out;

    cudaFuncSetAttribute(k_mma<D_N, true>,  cudaFuncAttributeMaxDynamicSharedMemorySize, SMEM_TOTAL);
    cudaFuncSetAttribute(k_mma<B_N, false>, cudaFuncAttributeMaxDynamicSharedMemorySize, SMEM_TOTAL);

    k_prep<<<(B_N + 255) / 256, 256>>>(y, c, fs);
    k_lnorm<<<B_N, 256>>>(x);
    k_transpose<<<dim3(B_N / 32, D_N / 32), 256>>>(x);

    // GEMM1: S = Xn.Xn^T (M=N=4096, K=2048), fused mask+exp+rowsum
    k_mma<D_N, true><<<dim3(B_N / BTN, B_N / BTM), 256, SMEM_TOTAL>>>(nullptr);
    // GEMM2: recon = expS . x (M=4096, N=2048, K=4096), fused 1/rowsum+blend
    k_mma<B_N, false><<<dim3(D_N / BTN, B_N / BTM), 256, SMEM_TOTAL>>>(x);

    k_mixx<<<(B_N * (D_N / 4) + 255) / 256, 256>>>(alpha, beta, out);
    k_mixy<<<(B_N * C_N + 255) / 256, 256>>>(alpha, beta, y, out);
}

// round 8
// speedup vs baseline: 1.3106x; 1.3106x over previous
#include <cuda_runtime.h>
#include <cuda_bf16.h>
#include <stdint.h>
#include <math.h>

#define B_N 4096
#define D_N 2048
#define C_N 64

#define BT 128            // CTA tile M = N = 128
#define BKS 64            // K per stage (bf16 elems) = 128 bytes per row
#define STAGES 3
#define A_TILE_B (BT*128)               // 16384 bytes
#define STAGE_B  (2*A_TILE_B)           // 32768 bytes
#define SMEM_TOTAL (1024 + STAGES*STAGE_B)   // 99328
#define TPAD 136          // transposed-bounce row stride (bf16 elems), 272B = 16B multiple

// ---------------- scratch (static device globals) ----------------
__device__ __align__(128) __nv_bfloat16 g_xbf[B_N * D_N];            // 16 MB
__device__ __align__(128) __nv_bfloat16 g_xT[D_N * B_N];             // 16 MB
__device__ __align__(128) __nv_bfloat16 g_expSbf[(size_t)B_N * B_N]; // 32 MB
__device__ __align__(128) float g_R[B_N * D_N];                      // 32 MB
__device__ float g_rowsum[B_N];
__device__ float g_keep[B_N];
__device__ float g_contrib[B_N];

// ---------------- PTX helpers (sm_80+ generic ISA only) ----------------
__device__ __forceinline__ uint32_t smem_u32(const void* p) {
    uint32_t a;
    asm("{ .reg .u64 t; cvta.to.shared.u64 t, %1; cvt.u32.u64 %0, t; }" : "=r"(a) : "l"(p));
    return a;
}
__device__ __forceinline__ void cp16(uint32_t s, const void* g) {
    asm volatile("cp.async.cg.shared.global [%0], [%1], 16;" :: "r"(s), "l"(g));
}
__device__ __forceinline__ void cp_commit() { asm volatile("cp.async.commit_group;"); }
__device__ __forceinline__ void cp_wait1()  { asm volatile("cp.async.wait_group 1;"); }

__device__ __forceinline__ void ldsm4(uint32_t* r, uint32_t addr) {
    asm volatile("ldmatrix.sync.aligned.m8n8.x4.shared.b16 {%0,%1,%2,%3}, [%4];"
        : "=r"(r[0]), "=r"(r[1]), "=r"(r[2]), "=r"(r[3]) : "r"(addr));
}
__device__ __forceinline__ void mma_bf16(float* c, const uint32_t* a, uint32_t b0, uint32_t b1) {
    asm volatile(
        "mma.sync.aligned.m16n8k16.row.col.f32.bf16.bf16.f32 "
        "{%0,%1,%2,%3}, {%4,%5,%6,%7}, {%8,%9}, {%0,%1,%2,%3};"
        : "+f"(c[0]), "+f"(c[1]), "+f"(c[2]), "+f"(c[3])
        : "r"(a[0]), "r"(a[1]), "r"(a[2]), "r"(a[3]), "r"(b0), "r"(b1));
}

// ---------------- small kernels ----------------
__global__ void k_prep(const int* __restrict__ y, const float* __restrict__ c,
                       const int* __restrict__ fs) {
    int i = blockIdx.x * blockDim.x + threadIdx.x;
    if (i < B_N) {
        int cls = y[i];
        g_contrib[i] = c[cls];
        g_keep[i] = fs[cls] ? 0.0f : 1.0f;
        g_rowsum[i] = 0.0f;
    }
}

__global__ __launch_bounds__(256) void k_lnorm(const float* __restrict__ x) {
    int row = blockIdx.x;
    const float* xr = x + (size_t)row * D_N;
    float s = 0.f, s2 = 0.f;
    for (int d = threadIdx.x; d < D_N; d += 256) {
        float v = xr[d];
        s += v; s2 += v * v;
    }
    __shared__ float sh[34];
    #pragma unroll
    for (int o = 16; o > 0; o >>= 1) {
        s  += __shfl_down_sync(0xffffffffu, s, o);
        s2 += __shfl_down_sync(0xffffffffu, s2, o);
    }
    int w = threadIdx.x >> 5, l = threadIdx.x & 31;
    if (l == 0) { sh[w] = s; sh[8 + w] = s2; }
    __syncthreads();
    if (threadIdx.x == 0) {
        float S = 0.f, S2 = 0.f;
        #pragma unroll
        for (int i = 0; i < 8; i++) { S += sh[i]; S2 += sh[8 + i]; }
        float mu = S / (float)D_N;
        float var = S2 / (float)D_N - mu * mu;
        sh[32] = mu;
        sh[33] = rsqrtf(var + 1e-5f) * rsqrtf((float)D_N);
    }
    __syncthreads();
    float mu = sh[32], sc = sh[33];
    __nv_bfloat16* xo = g_xbf + (size_t)row * D_N;
    for (int d = threadIdx.x; d < D_N; d += 256)
        xo[d] = __float2bfloat16((xr[d] - mu) * sc);
}

// x [B_N, D_N] fp32 -> g_xT [D_N, B_N] bf16
__global__ __launch_bounds__(256) void k_transpose(const float* __restrict__ x) {
    __shared__ float tile[32][33];
    int bk = blockIdx.x * 32;   // over B_N
    int bn = blockIdx.y * 32;   // over D_N
    int tx = threadIdx.x & 31, ty = threadIdx.x >> 5;
    #pragma unroll
    for (int i = 0; i < 32; i += 8)
        tile[ty + i][tx] = x[(size_t)(bk + ty + i) * D_N + bn + tx];
    __syncthreads();
    #pragma unroll
    for (int i = 0; i < 32; i += 8)
        g_xT[(size_t)(bn + ty + i) * B_N + bk + tx] = __float2bfloat16(tile[tx][ty + i]);
}

// ---------------- mma.sync GEMM: C[MxN] = A[M,K] . B[N,K]^T ----------------
// R4 pipeline (best config: 2 CTAs/SM, 8 warps, warp tile 64x32).
// EPI1 now triangular: grid 32x32, CTAs with bn<bm exit. Off-diagonal CTAs
// write their tile AND its transpose (per-direction masks), with column-sum
// atomics for the mirrored rows and an smem bounce for coalesced T-stores.
template<int KTOT, bool EPI1>
__global__ __launch_bounds__(256, 2) void k_mma(const float* __restrict__ x) {
    const int bm = blockIdx.y, bn = blockIdx.x;
    if (EPI1 && bn < bm) return;   // symmetry: only upper-triangular blocks

    extern __shared__ char smem[];
    const uint32_t smem_raw = smem_u32(smem);
    const uint32_t tiles0 = (smem_raw + 1023u) & ~1023u;
    const int t = threadIdx.x;
    const int wid = t >> 5, lane = t & 31;
    const int KC = KTOT / BKS;

    const __nv_bfloat16* A  = EPI1 ? g_xbf : g_expSbf;
    const __nv_bfloat16* Bm = EPI1 ? g_xbf : g_xT;

    const int warp_m0 = (wid >> 2) * 64;
    const int warp_n0 = (wid & 3) * 32;
    const int rowA0 = bm * BT;
    const int rowB0 = bn * BT;

    uint32_t sA[STAGES], sB[STAGES];
    #pragma unroll
    for (int s = 0; s < STAGES; s++) {
        sA[s] = tiles0 + (uint32_t)s * STAGE_B;
        sB[s] = sA[s] + A_TILE_B;
    }

    const int lr0 = t >> 3;      // 0..31
    const int cc = t & 7;        // 16B chunk in 128B row

    #define LOAD_STAGE(sidx, k0elem) do {                                              \
        _Pragma("unroll")                                                              \
        for (int _i = 0; _i < 4; _i++) {                                               \
            int _lr = lr0 + _i * 32;                                                   \
            uint32_t _soff = (uint32_t)(_lr * 128 + ((cc ^ (_lr & 7)) * 16));          \
            cp16(sA[sidx] + _soff, A  + (size_t)(rowA0 + _lr) * KTOT + (k0elem) + cc * 8); \
            cp16(sB[sidx] + _soff, Bm + (size_t)(rowB0 + _lr) * KTOT + (k0elem) + cc * 8); \
        }                                                                              \
    } while (0)

    #pragma unroll
    for (int p = 0; p < STAGES - 1; p++) {
        LOAD_STAGE(p, p * BKS);
        cp_commit();
    }

    float acc[4][4][4];
    #pragma unroll
    for (int i = 0; i < 4; i++)
        #pragma unroll
        for (int j = 0; j < 4; j++)
            #pragma unroll
            for (int r = 0; r < 4; r++) acc[i][j][r] = 0.f;

    const int lrow = lane & 15;
    const int lhal = lane >> 4;
    uint32_t aoff[4], boff[2];
    #pragma unroll
    for (int im = 0; im < 4; im++) {
        int r = warp_m0 + im * 16 + lrow;
        aoff[im] = (uint32_t)(r * 128 + ((lhal ^ (r & 7)) << 4));
    }
    #pragma unroll
    for (int ib = 0; ib < 2; ib++) {
        int r = warp_n0 + ib * 16 + lrow;
        boff[ib] = (uint32_t)(r * 128 + ((lhal ^ (r & 7)) << 4));
    }

    for (int c = 0; c < KC; c++) {
        cp_wait1();
        __syncthreads();
        if (c + STAGES - 1 < KC) LOAD_STAGE((c + STAGES - 1) % STAGES, (c + STAGES - 1) * BKS);
        cp_commit();

        const uint32_t bufA = sA[c % STAGES];
        const uint32_t bufB = sB[c % STAGES];
        uint32_t aBase[4], bBase[2];
        #pragma unroll
        for (int im = 0; im < 4; im++) aBase[im] = bufA + aoff[im];
        #pragma unroll
        for (int ib = 0; ib < 2; ib++) bBase[ib] = bufB + boff[ib];

        #pragma unroll
        for (int kk = 0; kk < 4; kk++) {
            uint32_t a[4][4], b[2][4];
            #pragma unroll
            for (int im = 0; im < 4; im++)
                ldsm4(a[im], aBase[im] ^ (uint32_t)(kk << 5));
            #pragma unroll
            for (int ib = 0; ib < 2; ib++)
                ldsm4(b[ib], bBase[ib] ^ (uint32_t)(kk << 5));
            #pragma unroll
            for (int im = 0; im < 4; im++) {
                #pragma unroll
                for (int ib = 0; ib < 2; ib++) {
                    mma_bf16(acc[im][ib * 2 + 0], a[im], b[ib][0], b[ib][2]);
                    mma_bf16(acc[im][ib * 2 + 1], a[im], b[ib][1], b[ib][3]);
                }
            }
        }
    }

    // ---- epilogue ----
    const int lq = lane >> 2;
    const int lp = lane & 3;
    int colg[4];
    #pragma unroll
    for (int j = 0; j < 4; j++)
        colg[j] = rowB0 + warp_n0 + (j >> 1) * 16 + (j & 1) * 8 + 2 * lp;

    if (EPI1) {
        const bool diag = (bm == bn);
        // stage buffers are dead after this barrier; reuse as transpose bounce
        __syncthreads();
        __nv_bfloat16* tsm = reinterpret_cast<__nv_bfloat16*>(smem + (tiles0 - smem_raw));

        float kp0[4], kp1[4];
        #pragma unroll
        for (int j = 0; j < 4; j++) { kp0[j] = g_keep[colg[j]]; kp1[j] = g_keep[colg[j] + 1]; }
        float cs[8];
        #pragma unroll
        for (int k2 = 0; k2 < 8; k2++) cs[k2] = 0.f;

        #pragma unroll
        for (int im = 0; im < 4; im++) {
            #pragma unroll
            for (int h = 0; h < 2; h++) {
                int row = rowA0 + warp_m0 + im * 16 + h * 8 + lq;
                float kr = g_keep[row];
                float rs = 0.f;
                #pragma unroll
                for (int j = 0; j < 4; j++) {
                    int c0 = colg[j], c1 = c0 + 1;
                    float e0 = __expf(acc[im][j][2 * h + 0]);
                    float e1 = __expf(acc[im][j][2 * h + 1]);
                    // normal direction: stored(row, c) = keep[c]*(c!=row)*e
                    float v0 = (c0 == row ? 0.f : kp0[j]) * e0;
                    float v1 = (c1 == row ? 0.f : kp1[j]) * e1;
                    __nv_bfloat16 b0 = __float2bfloat16(v0);
                    __nv_bfloat16 b1 = __float2bfloat16(v1);
                    rs += __bfloat162float(b0) + __bfloat162float(b1);
                    __nv_bfloat162 p2(b0, b1);
                    *reinterpret_cast<uint32_t*>(g_expSbf + (size_t)row * B_N + c0) =
                        *reinterpret_cast<uint32_t*>(&p2);
                    if (!diag) {
                        // mirrored direction: stored(c, row) = keep[row]*(c!=row)*e
                        float t0f = (c0 == row ? 0.f : kr) * e0;
                        float t1f = (c1 == row ? 0.f : kr) * e1;
                        __nv_bfloat16 t0 = __float2bfloat16(t0f);
                        __nv_bfloat16 t1 = __float2bfloat16(t1f);
                        cs[2 * j]     += __bfloat162float(t0);
                        cs[2 * j + 1] += __bfloat162float(t1);
                        int rl = row - rowA0;
                        tsm[(c0 - rowB0) * TPAD + rl] = t0;
                        tsm[(c1 - rowB0) * TPAD + rl] = t1;
                    }
                }
                rs += __shfl_xor_sync(0xffffffffu, rs, 1);
                rs += __shfl_xor_sync(0xffffffffu, rs, 2);
                if (lp == 0) atomicAdd(&g_rowsum[row], rs);
            }
        }

        if (!diag) {
            // column sums -> rowsum of mirrored rows (reduce over lq lanes)
            #pragma unroll
            for (int k2 = 0; k2 < 8; k2++) {
                cs[k2] += __shfl_xor_sync(0xffffffffu, cs[k2], 4);
                cs[k2] += __shfl_xor_sync(0xffffffffu, cs[k2], 8);
                cs[k2] += __shfl_xor_sync(0xffffffffu, cs[k2], 16);
            }
            if (lane < 4) {
                #pragma unroll
                for (int j = 0; j < 4; j++) {
                    atomicAdd(&g_rowsum[colg[j]],     cs[2 * j]);
                    atomicAdd(&g_rowsum[colg[j] + 1], cs[2 * j + 1]);
                }
            }
            __syncthreads();
            // coalesced flush of the transposed tile
            const int cl0 = t >> 4;         // 0..15
            const int ch = t & 15;          // 0..15 (16B chunks of the 256B row)
            #pragma unroll
            for (int it = 0; it < 8; it++) {
                int cl = cl0 + it * 16;     // local transposed row (= original col)
                uint4 v = *reinterpret_cast<const uint4*>(tsm + cl * TPAD + ch * 8);
                *reinterpret_cast<uint4*>(g_expSbf + (size_t)(rowB0 + cl) * B_N + rowA0 + ch * 8) = v;
            }
        }
    } else {
        #pragma unroll
        for (int im = 0; im < 4; im++) {
            #pragma unroll
            for (int h = 0; h < 2; h++) {
                int row = rowA0 + warp_m0 + im * 16 + h * 8 + lq;
                float ct = g_contrib[row];
                float s1 = ct / g_rowsum[row];     // fused reciprocal
                float s2 = 1.0f - ct;
                #pragma unroll
                for (int j = 0; j < 4; j++) {
                    const float2 xv = *(const float2*)(x + (size_t)row * D_N + colg[j]);
                    float2 o;
                    o.x = acc[im][j][2 * h + 0] * s1 + xv.x * s2;
                    o.y = acc[im][j][2 * h + 1] * s1 + xv.y * s2;
                    *(float2*)(g_R + (size_t)row * D_N + colg[j]) = o;
                }
            }
        }
    }
    #undef LOAD_STAGE
}

// ---------------- mix kernels ----------------
__global__ __launch_bounds__(256) void k_mixx(const float* __restrict__ alpha,
                                              const int* __restrict__ beta,
                                              float* __restrict__ out) {
    int idx = blockIdx.x * blockDim.x + threadIdx.x;
    const int nd4 = D_N / 4;
    if (idx < B_N * nd4) {
        int i = idx / nd4;
        int d4 = idx - i * nd4;
        float a = alpha[i];
        float na = 1.0f - a;
        int bi = beta[i];
        const float4* R4 = (const float4*)g_R;
        float4 r1 = R4[(size_t)i * nd4 + d4];
        float4 r2 = R4[(size_t)bi * nd4 + d4];
        float4 o;
        o.x = a * r1.x + na * r2.x;
        o.y = a * r1.y + na * r2.y;
        o.z = a * r1.z + na * r2.z;
        o.w = a * r1.w + na * r2.w;
        ((float4*)out)[idx] = o;
    }
}

__global__ void k_mixy(const float* __restrict__ alpha,
                       const int* __restrict__ beta,
                       const int* __restrict__ y,
                       float* __restrict__ out) {
    int idx = blockIdx.x * blockDim.x + threadIdx.x;
    if (idx < B_N * C_N) {
        int i = idx / C_N;
        int k = idx - i * C_N;
        float a = alpha[i];
        int bi = beta[i];
        float v = a * (k == y[i] ? 1.0f : 0.0f) + (1.0f - a) * (k == y[bi] ? 1.0f : 0.0f);
        out[(size_t)B_N * D_N + idx] = v;
    }
}

extern "C" void kernel_launch(void* const* d_in, const int* in_sizes, int n_in,
                              void* d_out, int out_size) {
    const float* x     = (const float*)d_in[0];
    const int*   y     = (const int*)  d_in[1];
    const float* alpha = (const float*)d_in[2];
    const int*   beta  = (const int*)  d_in[3];
    const float* c     = (const float*)d_in[4];
    const int*   fs    = (const int*)  d_in[5];
    float* out = (float*)d_out;

    cudaFuncSetAttribute(k_mma<D_N, true>,  cudaFuncAttributeMaxDynamicSharedMemorySize, SMEM_TOTAL);
    cudaFuncSetAttribute(k_mma<B_N, false>, cudaFuncAttributeMaxDynamicSharedMemorySize, SMEM_TOTAL);

    k_prep<<<(B_N + 255) / 256, 256>>>(y, c, fs);
    k_lnorm<<<B_N, 256>>>(x);
    k_transpose<<<dim3(B_N / 32, D_N / 32), 256>>>(x);

    // GEMM1 (triangular): S = Xn.Xn^T, fused mask+exp+rowsum, tile+transpose stores
    k_mma<D_N, true><<<dim3(B_N / BT, B_N / BT), 256, SMEM_TOTAL>>>(nullptr);
    // GEMM2: recon = expS . x (M=4096, N=2048, K=4096), fused 1/rowsum+blend
    k_mma<B_N, false><<<dim3(D_N / BT, B_N / BT), 256, SMEM_TOTAL>>>(x);

    k_mixx<<<(B_N * (D_N / 4) + 255) / 256, 256>>>(alpha, beta, out);
    k_mixy<<<(B_N * C_N + 255) / 256, 256>>>(alpha, beta, y, out);
}

// round 9
// speedup vs baseline: 1.4207x; 1.0840x over previous
#include <cuda_runtime.h>
#include <cuda_bf16.h>
#include <stdint.h>
#include <math.h>

#define B_N 4096
#define D_N 2048
#define C_N 64

#define BT 128            // CTA tile M = N = 128
#define BKS 64            // K per stage (bf16 elems) = 128 bytes per row
#define STAGES 3
#define A_TILE_B (BT*128)               // 16384 bytes
#define STAGE_B  (2*A_TILE_B)           // 32768 bytes
#define SMEM_TOTAL (1024 + STAGES*STAGE_B)   // 99328
#define TPAD 136          // transposed-bounce row stride (bf16 elems)

#define G1_BLOCKS 1024    // 32x32 triangular grid (empties exit)
#define G2_BLOCKS 512     // 32 (m) x 16 (n)

// ---------------- scratch (static device globals) ----------------
__device__ __align__(128) __nv_bfloat16 g_xbf[B_N * D_N];            // 16 MB
__device__ __align__(128) __nv_bfloat16 g_xT[D_N * B_N];             // 16 MB
__device__ __align__(128) __nv_bfloat16 g_expSbf[(size_t)B_N * B_N]; // 32 MB
__device__ __align__(128) float g_R[B_N * D_N];                      // 32 MB
__device__ float g_rowsum[B_N];
__device__ float g_keep[B_N];
__device__ float g_contrib[B_N];
__device__ int   g_cnt[32];          // per row-block readiness counters

// ---------------- PTX helpers (sm_80+ generic ISA only) ----------------
__device__ __forceinline__ uint32_t smem_u32(const void* p) {
    uint32_t a;
    asm("{ .reg .u64 t; cvta.to.shared.u64 t, %1; cvt.u32.u64 %0, t; }" : "=r"(a) : "l"(p));
    return a;
}
__device__ __forceinline__ void cp16(uint32_t s, const void* g) {
    asm volatile("cp.async.cg.shared.global [%0], [%1], 16;" :: "r"(s), "l"(g));
}
__device__ __forceinline__ void cp_commit() { asm volatile("cp.async.commit_group;"); }
__device__ __forceinline__ void cp_wait1()  { asm volatile("cp.async.wait_group 1;"); }

__device__ __forceinline__ void ldsm4(uint32_t* r, uint32_t addr) {
    asm volatile("ldmatrix.sync.aligned.m8n8.x4.shared.b16 {%0,%1,%2,%3}, [%4];"
        : "=r"(r[0]), "=r"(r[1]), "=r"(r[2]), "=r"(r[3]) : "r"(addr));
}
__device__ __forceinline__ void mma_bf16(float* c, const uint32_t* a, uint32_t b0, uint32_t b1) {
    asm volatile(
        "mma.sync.aligned.m16n8k16.row.col.f32.bf16.bf16.f32 "
        "{%0,%1,%2,%3}, {%4,%5,%6,%7}, {%8,%9}, {%0,%1,%2,%3};"
        : "+f"(c[0]), "+f"(c[1]), "+f"(c[2]), "+f"(c[3])
        : "r"(a[0]), "r"(a[1]), "r"(a[2]), "r"(a[3]), "r"(b0), "r"(b1));
}
__device__ __forceinline__ uint32_t ld_acq(const int* p) {
    uint32_t v;
    asm volatile("ld.acquire.gpu.global.u32 %0, [%1];" : "=r"(v) : "l"(p) : "memory");
    return v;
}

// ---------------- small kernels ----------------
__global__ void k_prep(const int* __restrict__ y, const float* __restrict__ c,
                       const int* __restrict__ fs) {
    int i = blockIdx.x * blockDim.x + threadIdx.x;
    if (i < B_N) {
        int cls = y[i];
        g_contrib[i] = c[cls];
        g_keep[i] = fs[cls] ? 0.0f : 1.0f;
        g_rowsum[i] = 0.0f;
        if (i < 32) g_cnt[i] = 0;
    }
}

// fused: LayerNorm -> g_xbf  AND  transpose -> g_xT (x read from DRAM once)
__global__ __launch_bounds__(256) void k_prepx(const float* __restrict__ x) {
    __shared__ float mus[32], scs[32];
    __shared__ float tile[32][33];
    const int row0 = blockIdx.x * 32;
    const int wid = threadIdx.x >> 5, lane = threadIdx.x & 31;

    // stats: each warp handles 4 rows
    #pragma unroll
    for (int rr = 0; rr < 4; rr++) {
        int r = wid * 4 + rr;
        const float* xr = x + (size_t)(row0 + r) * D_N;
        float s = 0.f, s2 = 0.f;
        for (int d = lane; d < D_N; d += 32) {
            float v = xr[d];
            s += v; s2 += v * v;
        }
        #pragma unroll
        for (int o = 16; o > 0; o >>= 1) {
            s  += __shfl_down_sync(0xffffffffu, s, o);
            s2 += __shfl_down_sync(0xffffffffu, s2, o);
        }
        if (lane == 0) {
            float mu = s / (float)D_N;
            float var = s2 / (float)D_N - mu * mu;
            mus[r] = mu;
            scs[r] = rsqrtf(var + 1e-5f) * rsqrtf((float)D_N);
        }
    }
    __syncthreads();

    const int tx = threadIdx.x & 31, ty = threadIdx.x >> 5;  // 32x8
    for (int ct = 0; ct < D_N / 32; ct++) {
        int c0 = ct * 32;
        #pragma unroll
        for (int i = 0; i < 32; i += 8) {
            int r = ty + i;
            float v = x[(size_t)(row0 + r) * D_N + c0 + tx];
            tile[r][tx] = v;
            g_xbf[(size_t)(row0 + r) * D_N + c0 + tx] =
                __float2bfloat16((v - mus[r]) * scs[r]);
        }
        __syncthreads();
        #pragma unroll
        for (int i = 0; i < 32; i += 8)
            g_xT[(size_t)(c0 + ty + i) * B_N + row0 + tx] = __float2bfloat16(tile[tx][ty + i]);
        __syncthreads();
    }
}

// ---------------- fused GEMM1 (triangular) + GEMM2, one launch ----------------
// bids [0,1024): GEMM1 tile (bm,bn) upper triangle; mask+exp+rowsum epilogue,
//   tile + transposed-tile stores, then release cnt[bm], cnt[bn].
// bids [1024,1536): GEMM2 block (m,n); acquire-spin on cnt[m]==32, then
//   recon with fused 1/rowsum + residual blend -> g_R.
__global__ __launch_bounds__(256, 2) void k_fused(const float* __restrict__ x) {
    const int bid = blockIdx.x;
    const bool g1 = bid < G1_BLOCKS;
    int bm, bn, KTOT;
    const __nv_bfloat16 *A, *Bmat;
    if (g1) {
        bm = bid >> 5; bn = bid & 31;
        if (bn < bm) return;                 // symmetry: upper triangle only
        KTOT = D_N; A = g_xbf; Bmat = g_xbf;
    } else {
        int b2 = bid - G1_BLOCKS;
        bm = b2 >> 4; bn = b2 & 15;          // m-major: matches cnt readiness order
        KTOT = B_N; A = g_expSbf; Bmat = g_xT;
        if (threadIdx.x == 0) {
            while (ld_acq(&g_cnt[bm]) < 32) __nanosleep(256);
        }
        __syncthreads();
    }

    extern __shared__ char smem[];
    const uint32_t smem_raw = smem_u32(smem);
    const uint32_t tiles0 = (smem_raw + 1023u) & ~1023u;
    const int t = threadIdx.x;
    const int wid = t >> 5, lane = t & 31;
    const int KC = KTOT / BKS;

    const int warp_m0 = (wid >> 2) * 64;
    const int warp_n0 = (wid & 3) * 32;
    const int rowA0 = bm * BT;
    const int rowB0 = bn * BT;

    uint32_t sA[STAGES], sB[STAGES];
    #pragma unroll
    for (int s = 0; s < STAGES; s++) {
        sA[s] = tiles0 + (uint32_t)s * STAGE_B;
        sB[s] = sA[s] + A_TILE_B;
    }

    const int lr0 = t >> 3;
    const int cc = t & 7;

    const __nv_bfloat16* gA = A    + (size_t)(rowA0 + lr0) * KTOT + cc * 8;
    const __nv_bfloat16* gB = Bmat + (size_t)(rowB0 + lr0) * KTOT + cc * 8;

    #define LOAD_STAGE(sidx, k0elem) do {                                              \
        _Pragma("unroll")                                                              \
        for (int _i = 0; _i < 4; _i++) {                                               \
            int _lr = lr0 + _i * 32;                                                   \
            uint32_t _soff = (uint32_t)(_lr * 128 + ((cc ^ (_lr & 7)) * 16));          \
            cp16(sA[sidx] + _soff, gA + (size_t)_i * 32 * KTOT + (k0elem));            \
            cp16(sB[sidx] + _soff, gB + (size_t)_i * 32 * KTOT + (k0elem));            \
        }                                                                              \
    } while (0)

    #pragma unroll
    for (int p = 0; p < STAGES - 1; p++) {
        LOAD_STAGE(p, p * BKS);
        cp_commit();
    }

    float acc[4][4][4];
    #pragma unroll
    for (int i = 0; i < 4; i++)
        #pragma unroll
        for (int j = 0; j < 4; j++)
            #pragma unroll
            for (int r = 0; r < 4; r++) acc[i][j][r] = 0.f;

    const int lrow = lane & 15;
    const int lhal = lane >> 4;
    uint32_t aoff[4], boff[2];
    #pragma unroll
    for (int im = 0; im < 4; im++) {
        int r = warp_m0 + im * 16 + lrow;
        aoff[im] = (uint32_t)(r * 128 + ((lhal ^ (r & 7)) << 4));
    }
    #pragma unroll
    for (int ib = 0; ib < 2; ib++) {
        int r = warp_n0 + ib * 16 + lrow;
        boff[ib] = (uint32_t)(r * 128 + ((lhal ^ (r & 7)) << 4));
    }

    for (int c = 0; c < KC; c++) {
        cp_wait1();
        __syncthreads();
        if (c + STAGES - 1 < KC) LOAD_STAGE((c + STAGES - 1) % STAGES, (c + STAGES - 1) * BKS);
        cp_commit();

        const uint32_t bufA = sA[c % STAGES];
        const uint32_t bufB = sB[c % STAGES];
        uint32_t aBase[4], bBase[2];
        #pragma unroll
        for (int im = 0; im < 4; im++) aBase[im] = bufA + aoff[im];
        #pragma unroll
        for (int ib = 0; ib < 2; ib++) bBase[ib] = bufB + boff[ib];

        #pragma unroll
        for (int kk = 0; kk < 4; kk++) {
            uint32_t a[4][4], b[2][4];
            #pragma unroll
            for (int im = 0; im < 4; im++)
                ldsm4(a[im], aBase[im] ^ (uint32_t)(kk << 5));
            #pragma unroll
            for (int ib = 0; ib < 2; ib++)
                ldsm4(b[ib], bBase[ib] ^ (uint32_t)(kk << 5));
            #pragma unroll
            for (int im = 0; im < 4; im++) {
                #pragma unroll
                for (int ib = 0; ib < 2; ib++) {
                    mma_bf16(acc[im][ib * 2 + 0], a[im], b[ib][0], b[ib][2]);
                    mma_bf16(acc[im][ib * 2 + 1], a[im], b[ib][1], b[ib][3]);
                }
            }
        }
    }

    // ---- epilogue ----
    const int lq = lane >> 2;
    const int lp = lane & 3;
    int colg[4];
    #pragma unroll
    for (int j = 0; j < 4; j++)
        colg[j] = rowB0 + warp_n0 + (j >> 1) * 16 + (j & 1) * 8 + 2 * lp;

    if (g1) {
        const bool diag = (bm == bn);
        __syncthreads();   // stage buffers dead; reuse as transpose bounce
        __nv_bfloat16* tsm = reinterpret_cast<__nv_bfloat16*>(smem + (tiles0 - smem_raw));

        float kp0[4], kp1[4];
        #pragma unroll
        for (int j = 0; j < 4; j++) { kp0[j] = g_keep[colg[j]]; kp1[j] = g_keep[colg[j] + 1]; }
        float cs[8];
        #pragma unroll
        for (int k2 = 0; k2 < 8; k2++) cs[k2] = 0.f;

        #pragma unroll
        for (int im = 0; im < 4; im++) {
            #pragma unroll
            for (int h = 0; h < 2; h++) {
                int row = rowA0 + warp_m0 + im * 16 + h * 8 + lq;
                float kr = g_keep[row];
                float rs = 0.f;
                #pragma unroll
                for (int j = 0; j < 4; j++) {
                    int c0 = colg[j], c1 = c0 + 1;
                    float e0 = __expf(acc[im][j][2 * h + 0]);
                    float e1 = __expf(acc[im][j][2 * h + 1]);
                    float v0 = (c0 == row ? 0.f : kp0[j]) * e0;
                    float v1 = (c1 == row ? 0.f : kp1[j]) * e1;
                    __nv_bfloat16 b0 = __float2bfloat16(v0);
                    __nv_bfloat16 b1 = __float2bfloat16(v1);
                    rs += __bfloat162float(b0) + __bfloat162float(b1);
                    __nv_bfloat162 p2(b0, b1);
                    *reinterpret_cast<uint32_t*>(g_expSbf + (size_t)row * B_N + c0) =
                        *reinterpret_cast<uint32_t*>(&p2);
                    if (!diag) {
                        float t0f = (c0 == row ? 0.f : kr) * e0;
                        float t1f = (c1 == row ? 0.f : kr) * e1;
                        __nv_bfloat16 t0 = __float2bfloat16(t0f);
                        __nv_bfloat16 t1 = __float2bfloat16(t1f);
                        cs[2 * j]     += __bfloat162float(t0);
                        cs[2 * j + 1] += __bfloat162float(t1);
                        int rl = row - rowA0;
                        tsm[(c0 - rowB0) * TPAD + rl] = t0;
                        tsm[(c1 - rowB0) * TPAD + rl] = t1;
                    }
                }
                rs += __shfl_xor_sync(0xffffffffu, rs, 1);
                rs += __shfl_xor_sync(0xffffffffu, rs, 2);
                if (lp == 0) atomicAdd(&g_rowsum[row], rs);
            }
        }

        if (!diag) {
            #pragma unroll
            for (int k2 = 0; k2 < 8; k2++) {
                cs[k2] += __shfl_xor_sync(0xffffffffu, cs[k2], 4);
                cs[k2] += __shfl_xor_sync(0xffffffffu, cs[k2], 8);
                cs[k2] += __shfl_xor_sync(0xffffffffu, cs[k2], 16);
            }
            if (lane < 4) {
                #pragma unroll
                for (int j = 0; j < 4; j++) {
                    atomicAdd(&g_rowsum[colg[j]],     cs[2 * j]);
                    atomicAdd(&g_rowsum[colg[j] + 1], cs[2 * j + 1]);
                }
            }
            __syncthreads();
            const int cl0 = t >> 4;
            const int ch = t & 15;
            #pragma unroll
            for (int it = 0; it < 8; it++) {
                int cl = cl0 + it * 16;
                uint4 v = *reinterpret_cast<const uint4*>(tsm + cl * TPAD + ch * 8);
                *reinterpret_cast<uint4*>(g_expSbf + (size_t)(rowB0 + cl) * B_N + rowA0 + ch * 8) = v;
            }
        }

        // release: publish completion of row blocks bm and bn
        __threadfence();
        __syncthreads();
        if (t == 0) {
            atomicAdd(&g_cnt[bm], 1);
            if (bm != bn) atomicAdd(&g_cnt[bn], 1);
        }
    } else {
        #pragma unroll
        for (int im = 0; im < 4; im++) {
            #pragma unroll
            for (int h = 0; h < 2; h++) {
                int row = rowA0 + warp_m0 + im * 16 + h * 8 + lq;
                float ct = g_contrib[row];
                float s1 = ct / g_rowsum[row];     // fused reciprocal
                float s2 = 1.0f - ct;
                #pragma unroll
                for (int j = 0; j < 4; j++) {
                    const float2 xv = *(const float2*)(x + (size_t)row * D_N + colg[j]);
                    float2 o;
                    o.x = acc[im][j][2 * h + 0] * s1 + xv.x * s2;
                    o.y = acc[im][j][2 * h + 1] * s1 + xv.y * s2;
                    *(float2*)(g_R + (size_t)row * D_N + colg[j]) = o;
                }
            }
        }
    }
    #undef LOAD_STAGE
}

// ---------------- mix kernels ----------------
__global__ __launch_bounds__(256) void k_mixx(const float* __restrict__ alpha,
                                              const int* __restrict__ beta,
                                              float* __restrict__ out) {
    int idx = blockIdx.x * blockDim.x + threadIdx.x;
    const int nd4 = D_N / 4;
    if (idx < B_N * nd4) {
        int i = idx / nd4;
        int d4 = idx - i * nd4;
        float a = alpha[i];
        float na = 1.0f - a;
        int bi = beta[i];
        const float4* R4 = (const float4*)g_R;
        float4 r1 = R4[(size_t)i * nd4 + d4];
        float4 r2 = R4[(size_t)bi * nd4 + d4];
        float4 o;
        o.x = a * r1.x + na * r2.x;
        o.y = a * r1.y + na * r2.y;
        o.z = a * r1.z + na * r2.z;
        o.w = a * r1.w + na * r2.w;
        ((float4*)out)[idx] = o;
    }
}

__global__ void k_mixy(const float* __restrict__ alpha,
                       const int* __restrict__ beta,
                       const int* __restrict__ y,
                       float* __restrict__ out) {
    int idx = blockIdx.x * blockDim.x + threadIdx.x;
    if (idx < B_N * C_N) {
        int i = idx / C_N;
        int k = idx - i * C_N;
        float a = alpha[i];
        int bi = beta[i];
        float v = a * (k == y[i] ? 1.0f : 0.0f) + (1.0f - a) * (k == y[bi] ? 1.0f : 0.0f);
        out[(size_t)B_N * D_N + idx] = v;
    }
}

extern "C" void kernel_launch(void* const* d_in, const int* in_sizes, int n_in,
                              void* d_out, int out_size) {
    const float* x     = (const float*)d_in[0];
    const int*   y     = (const int*)  d_in[1];
    const float* alpha = (const float*)d_in[2];
    const int*   beta  = (const int*)  d_in[3];
    const float* c     = (const float*)d_in[4];
    const int*   fs    = (const int*)  d_in[5];
    float* out = (float*)d_out;

    cudaFuncSetAttribute(k_fused, cudaFuncAttributeMaxDynamicSharedMemorySize, SMEM_TOTAL);

    k_prep<<<(B_N + 255) / 256, 256>>>(y, c, fs);
    k_prepx<<<B_N / 32, 256>>>(x);
    k_fused<<<G1_BLOCKS + G2_BLOCKS, 256, SMEM_TOTAL>>>(x);
    k_mixx<<<(B_N * (D_N / 4) + 255) / 256, 256>>>(alpha, beta, out);
    k_mixy<<<(B_N * C_N + 255) / 256, 256>>>(alpha, beta, y, out);
}